// round 1
// baseline (speedup 1.0000x reference)
#include <cuda_runtime.h>
#include <cuda_bf16.h>
#include <math.h>

// Problem constants
#define BATCH 4
#define SEQ   2048
#define HID   1024
#define MTOT  (BATCH * SEQ)   // 8192

// Scratch (device globals: allocation-free per harness rules)
__device__ float g_Q[(size_t)BATCH * SEQ * HID];
__device__ float g_K[(size_t)BATCH * SEQ * HID];
__device__ float g_V[(size_t)BATCH * SEQ * HID];
__device__ float g_S[(size_t)BATCH * SEQ * SEQ];
__device__ float g_C[(size_t)BATCH * SEQ * HID];

// ---------------------------------------------------------------------------
// Tiled SGEMM: C[M,N] = alpha * A[M,K] @ op(B) + bias
//   TB == false : B is [K,N] row-major (NN)
//   TB == true  : B is [N,K] row-major (NT, i.e. C = A @ B^T)
// Block tile 128x128, K-tile 8, 256 threads, 8x8 per-thread micro-tile.
// All of M, N divisible by 128; K divisible by 8. Batched via blockIdx.z.
// ---------------------------------------------------------------------------
template <bool TB>
__global__ __launch_bounds__(256) void gemm128(
    const float* __restrict__ A, const float* __restrict__ B,
    const float* __restrict__ bias, float* __restrict__ C,
    int M, int N, int Kd,
    size_t sA, size_t sB, size_t sC, float alpha)
{
    A += (size_t)blockIdx.z * sA;
    B += (size_t)blockIdx.z * sB;
    C += (size_t)blockIdx.z * sC;

    __shared__ float As[8][128];
    __shared__ float Bs[8][128];

    const int tid = threadIdx.x;
    const int tx = tid & 15;          // 0..15 (N direction)
    const int ty = tid >> 4;          // 0..15 (M direction)
    const int br = blockIdx.y * 128;
    const int bc = blockIdx.x * 128;

    // A-tile load map: 128 rows x 8 cols, float4 along K
    const int aRow = tid >> 1;        // 0..127
    const int aK   = (tid & 1) * 4;   // 0 or 4

    float acc[8][8];
#pragma unroll
    for (int i = 0; i < 8; ++i)
#pragma unroll
        for (int j = 0; j < 8; ++j) acc[i][j] = 0.f;

    for (int k0 = 0; k0 < Kd; k0 += 8) {
        // load A tile (transposed into As[k][m])
        float4 a4 = *reinterpret_cast<const float4*>(
            A + (size_t)(br + aRow) * Kd + (k0 + aK));
        As[aK + 0][aRow] = a4.x;
        As[aK + 1][aRow] = a4.y;
        As[aK + 2][aRow] = a4.z;
        As[aK + 3][aRow] = a4.w;

        if (!TB) {
            // B: [K,N] row-major; 8 rows x 128 cols, float4 along N
            const int bk  = tid >> 5;         // 0..7
            const int bc4 = (tid & 31) * 4;   // 0..124
            float4 b4 = *reinterpret_cast<const float4*>(
                B + (size_t)(k0 + bk) * N + (bc + bc4));
            *reinterpret_cast<float4*>(&Bs[bk][bc4]) = b4;
        } else {
            // B: [N,K] row-major; load 128 n-rows x 8 k-cols, float4 along K
            const int bn  = tid >> 1;         // 0..127
            const int bk4 = (tid & 1) * 4;    // 0 or 4
            float4 b4 = *reinterpret_cast<const float4*>(
                B + (size_t)(bc + bn) * Kd + (k0 + bk4));
            Bs[bk4 + 0][bn] = b4.x;
            Bs[bk4 + 1][bn] = b4.y;
            Bs[bk4 + 2][bn] = b4.z;
            Bs[bk4 + 3][bn] = b4.w;
        }
        __syncthreads();

#pragma unroll
        for (int kk = 0; kk < 8; ++kk) {
            float ra[8], rb[8];
            *reinterpret_cast<float4*>(&ra[0]) =
                *reinterpret_cast<const float4*>(&As[kk][ty * 4]);
            *reinterpret_cast<float4*>(&ra[4]) =
                *reinterpret_cast<const float4*>(&As[kk][64 + ty * 4]);
            *reinterpret_cast<float4*>(&rb[0]) =
                *reinterpret_cast<const float4*>(&Bs[kk][tx * 4]);
            *reinterpret_cast<float4*>(&rb[4]) =
                *reinterpret_cast<const float4*>(&Bs[kk][64 + tx * 4]);
#pragma unroll
            for (int i = 0; i < 8; ++i)
#pragma unroll
                for (int j = 0; j < 8; ++j)
                    acc[i][j] = fmaf(ra[i], rb[j], acc[i][j]);
        }
        __syncthreads();
    }

    // epilogue: split-quad mapping (rows: ty*4+i and 64+ty*4+i; cols likewise)
    const int gc0 = bc + tx * 4;
    const int gc1 = bc + 64 + tx * 4;
    float bb0[4], bb1[4];
#pragma unroll
    for (int j = 0; j < 4; ++j) {
        bb0[j] = bias ? bias[gc0 + j] : 0.f;
        bb1[j] = bias ? bias[gc1 + j] : 0.f;
    }
#pragma unroll
    for (int i = 0; i < 8; ++i) {
        const int gr = br + ((i < 4) ? (ty * 4 + i) : (64 + ty * 4 + (i - 4)));
        float4 v0, v1;
        v0.x = alpha * acc[i][0] + bb0[0];
        v0.y = alpha * acc[i][1] + bb0[1];
        v0.z = alpha * acc[i][2] + bb0[2];
        v0.w = alpha * acc[i][3] + bb0[3];
        v1.x = alpha * acc[i][4] + bb1[0];
        v1.y = alpha * acc[i][5] + bb1[1];
        v1.z = alpha * acc[i][6] + bb1[2];
        v1.w = alpha * acc[i][7] + bb1[3];
        *reinterpret_cast<float4*>(C + (size_t)gr * N + gc0) = v0;
        *reinterpret_cast<float4*>(C + (size_t)gr * N + gc1) = v1;
    }
}

// ---------------------------------------------------------------------------
// Row softmax over 2048 columns. One block (256 threads) per row; values kept
// in registers between the max and sum passes.
// ---------------------------------------------------------------------------
__global__ __launch_bounds__(256) void softmax2048(float* __restrict__ S)
{
    const int NC = SEQ;
    float* row = S + (size_t)blockIdx.x * NC;
    const int tid = threadIdx.x;

    float v[8];
    float m = -INFINITY;
#pragma unroll
    for (int i = 0; i < 8; ++i) {
        v[i] = row[tid + i * 256];
        m = fmaxf(m, v[i]);
    }

    __shared__ float red[256];
    red[tid] = m;
    __syncthreads();
#pragma unroll
    for (int s = 128; s > 0; s >>= 1) {
        if (tid < s) red[tid] = fmaxf(red[tid], red[tid + s]);
        __syncthreads();
    }
    m = red[0];
    __syncthreads();

    float sum = 0.f;
#pragma unroll
    for (int i = 0; i < 8; ++i) {
        v[i] = expf(v[i] - m);
        sum += v[i];
    }
    red[tid] = sum;
    __syncthreads();
#pragma unroll
    for (int s = 128; s > 0; s >>= 1) {
        if (tid < s) red[tid] += red[tid + s];
        __syncthreads();
    }
    const float inv = 1.0f / red[0];
#pragma unroll
    for (int i = 0; i < 8; ++i) row[tid + i * 256] = v[i] * inv;
}

// ---------------------------------------------------------------------------
extern "C" void kernel_launch(void* const* d_in, const int* in_sizes, int n_in,
                              void* d_out, int out_size)
{
    (void)in_sizes; (void)n_in; (void)out_size;

    const float* X  = (const float*)d_in[0];
    const float* Wq = (const float*)d_in[1];
    const float* bq = (const float*)d_in[2];
    const float* Wk = (const float*)d_in[3];
    const float* bk = (const float*)d_in[4];
    const float* Wv = (const float*)d_in[5];
    const float* bv = (const float*)d_in[6];
    const float* Wh = (const float*)d_in[7];
    const float* bh = (const float*)d_in[8];
    float* out = (float*)d_out;

    float *Q, *Kp, *V, *S, *C;
    cudaGetSymbolAddress((void**)&Q,  g_Q);
    cudaGetSymbolAddress((void**)&Kp, g_K);
    cudaGetSymbolAddress((void**)&V,  g_V);
    cudaGetSymbolAddress((void**)&S,  g_S);
    cudaGetSymbolAddress((void**)&C,  g_C);

    const dim3 blk(256);
    const float scale = 1.0f / 32.0f;   // 1/sqrt(1024)

    // QKV projections: [8192,1024] @ [1024,1024] + bias
    dim3 gp(HID / 128, MTOT / 128, 1);
    gemm128<false><<<gp, blk>>>(X, Wq, bq, Q,  MTOT, HID, HID, 0, 0, 0, 1.f);
    gemm128<false><<<gp, blk>>>(X, Wk, bk, Kp, MTOT, HID, HID, 0, 0, 0, 1.f);
    gemm128<false><<<gp, blk>>>(X, Wv, bv, V,  MTOT, HID, HID, 0, 0, 0, 1.f);

    // scores = scale * Q @ K^T, batched over 4
    dim3 gs(SEQ / 128, SEQ / 128, BATCH);
    gemm128<true><<<gs, blk>>>(Q, Kp, nullptr, S, SEQ, SEQ, HID,
                               (size_t)SEQ * HID, (size_t)SEQ * HID,
                               (size_t)SEQ * SEQ, scale);

    // softmax over rows
    softmax2048<<<BATCH * SEQ, blk>>>(S);

    // context = attn @ V, batched
    dim3 gc(HID / 128, SEQ / 128, BATCH);
    gemm128<false><<<gc, blk>>>(S, V, nullptr, C, SEQ, HID, SEQ,
                                (size_t)SEQ * SEQ, (size_t)SEQ * HID,
                                (size_t)SEQ * HID, 1.f);

    // y = context @ Wh + bh  -> d_out [8192, 1024]
    dim3 go(HID / 128, MTOT / 128, 1);
    gemm128<false><<<go, blk>>>(C, Wh, bh, out, MTOT, HID, HID, 0, 0, 0, 1.f);
}

// round 3
// speedup vs baseline: 2.4533x; 2.4533x over previous
#include <cuda_runtime.h>
#include <cuda_bf16.h>
#include <math.h>
#include <stdint.h>

#define BATCH 4
#define SEQ   2048
#define HID   1024
#define MTOT  (BATCH * SEQ)   // 8192

// ---------------------------------------------------------------------------
// Scratch (device globals; allocation-free per harness rules)
// ---------------------------------------------------------------------------
__device__ __nv_bfloat16 g_Xh[(size_t)MTOT * HID];
__device__ __nv_bfloat16 g_Xl[(size_t)MTOT * HID];

__device__ __nv_bfloat16 g_Wqh[HID * HID], g_Wql[HID * HID];
__device__ __nv_bfloat16 g_Wkh[HID * HID], g_Wkl[HID * HID];
__device__ __nv_bfloat16 g_Wvh[HID * HID], g_Wvl[HID * HID];
__device__ __nv_bfloat16 g_Whh[HID * HID], g_Whl[HID * HID];

__device__ __nv_bfloat16 g_Qh[(size_t)MTOT * HID], g_Ql[(size_t)MTOT * HID];
__device__ __nv_bfloat16 g_Kh[(size_t)MTOT * HID], g_Kl[(size_t)MTOT * HID];
__device__ float         g_Vf[(size_t)MTOT * HID];
__device__ __nv_bfloat16 g_Vth[(size_t)MTOT * HID], g_Vtl[(size_t)MTOT * HID];

__device__ float         g_Sf[(size_t)BATCH * SEQ * SEQ];
__device__ __nv_bfloat16 g_Sh[(size_t)BATCH * SEQ * SEQ], g_Sl[(size_t)BATCH * SEQ * SEQ];

__device__ __nv_bfloat16 g_Ch[(size_t)MTOT * HID], g_Cl[(size_t)MTOT * HID];

// ---------------------------------------------------------------------------
// helpers
// ---------------------------------------------------------------------------
__device__ __forceinline__ uint32_t smem_u32(const void* p) {
    uint32_t a;
    asm("{ .reg .u64 t; cvta.to.shared.u64 t, %1; cvt.u32.u64 %0, t; }"
        : "=r"(a) : "l"(p));
    return a;
}

__device__ __forceinline__ void cp16(uint32_t saddr, const void* gaddr) {
    asm volatile("cp.async.cg.shared.global [%0], [%1], 16;"
                 :: "r"(saddr), "l"(gaddr));
}
__device__ __forceinline__ void cp_commit() {
    asm volatile("cp.async.commit_group;" ::: "memory");
}
template <int N>
__device__ __forceinline__ void cp_wait() {
    asm volatile("cp.async.wait_group %0;" :: "n"(N) : "memory");
}

__device__ __forceinline__ void ldsm4(uint32_t addr, uint32_t& r0, uint32_t& r1,
                                      uint32_t& r2, uint32_t& r3) {
    asm volatile("ldmatrix.sync.aligned.m8n8.x4.shared.b16 {%0,%1,%2,%3}, [%4];"
                 : "=r"(r0), "=r"(r1), "=r"(r2), "=r"(r3) : "r"(addr));
}

__device__ __forceinline__ void mma16816(float* c, const uint32_t* a,
                                         uint32_t b0, uint32_t b1) {
    asm volatile(
        "mma.sync.aligned.m16n8k16.row.col.f32.bf16.bf16.f32 "
        "{%0,%1,%2,%3}, {%4,%5,%6,%7}, {%8,%9}, {%0,%1,%2,%3};"
        : "+f"(c[0]), "+f"(c[1]), "+f"(c[2]), "+f"(c[3])
        : "r"(a[0]), "r"(a[1]), "r"(a[2]), "r"(a[3]), "r"(b0), "r"(b1));
}

__device__ __forceinline__ void split2(float x, __nv_bfloat16& h, __nv_bfloat16& l) {
    h = __float2bfloat16(x);
    l = __float2bfloat16(x - __bfloat162float(h));
}

// ldmatrix x4 source address inside a [128 rows x 64B] swizzled tile.
// base_row: first row of the 16x16 block; ks: k-step (0/1); lane: 0..31
__device__ __forceinline__ uint32_t lds_addr(uint32_t tb, int base_row, int ks, int lane) {
    int r = base_row + ((lane >> 3) & 1) * 8 + (lane & 7);
    int c = (ks * 2 + (lane >> 4)) ^ ((r >> 1) & 3);
    return tb + (uint32_t)(r * 64 + c * 16);
}

// ---------------------------------------------------------------------------
// Emulated-fp32 NT GEMM via 3x bf16 mma.sync:
//   C[M,N] = alpha*(A @ B^T) + bias;  A:[M,K] hi/lo, B:[N,K] hi/lo (K-major)
// Block 128x128, Ktile 32, 8 warps (warp tile 64x32), cp.async double buffer.
// ---------------------------------------------------------------------------
#define GEMM_SMEM 65536   // 2 stages * 4 tiles * 8KB

template <bool SPLITOUT>
__global__ __launch_bounds__(256) void gemm_mma(
    const __nv_bfloat16* __restrict__ Ahp, const __nv_bfloat16* __restrict__ Alp,
    const __nv_bfloat16* __restrict__ Bhp, const __nv_bfloat16* __restrict__ Blp,
    const float* __restrict__ bias,
    float* __restrict__ Cf, __nv_bfloat16* __restrict__ Ch, __nv_bfloat16* __restrict__ Cl,
    int N, int K, size_t sA, size_t sB, size_t sC, float alpha)
{
    extern __shared__ char smem_raw[];
    const uint32_t smem = smem_u32(smem_raw);

    const int tid  = threadIdx.x;
    const int lane = tid & 31;
    const int warp = tid >> 5;
    const int wm = warp >> 2;          // 0..1  (M)
    const int wn = warp & 3;           // 0..3  (N)
    const int bn = blockIdx.x, bm = blockIdx.y, z = blockIdx.z;

    const __nv_bfloat16* pAh = Ahp + (size_t)z * sA + (size_t)bm * 128 * K;
    const __nv_bfloat16* pAl = Alp + (size_t)z * sA + (size_t)bm * 128 * K;
    const __nv_bfloat16* pBh = Bhp + (size_t)z * sB + (size_t)bn * 128 * K;
    const __nv_bfloat16* pBl = Blp + (size_t)z * sB + (size_t)bn * 128 * K;

    // per-thread cp.async source/dest mapping (2 chunks of 16B per tile)
    // chunk ch: row=ch>>2, c=ch&3 ; swizzled c' = c ^ ((row>>1)&3)
    auto stage_load = [&](uint32_t sb, int k0) {
#pragma unroll
        for (int h = 0; h < 2; ++h) {
            const int ch  = tid + h * 256;
            const int row = ch >> 2, c = ch & 3;
            const int cs  = c ^ ((row >> 1) & 3);
            const uint32_t so = (uint32_t)(row * 64 + cs * 16);
            const size_t   go = (size_t)row * K + k0 + c * 8;
            cp16(sb +     0 + so, pAh + go);
            cp16(sb +  8192 + so, pAl + go);
            cp16(sb + 16384 + so, pBh + go);
            cp16(sb + 24576 + so, pBl + go);
        }
    };

    float acc[4][4][4];
#pragma unroll
    for (int i = 0; i < 4; ++i)
#pragma unroll
        for (int j = 0; j < 4; ++j)
#pragma unroll
            for (int q = 0; q < 4; ++q) acc[i][j][q] = 0.f;

    const int KT = K >> 5;

    stage_load(smem, 0);
    cp_commit();

    for (int kt = 0; kt < KT; ++kt) {
        if (kt + 1 < KT) {
            stage_load(smem + (uint32_t)((kt + 1) & 1) * 32768, (kt + 1) * 32);
            cp_commit();
            cp_wait<1>();
        } else {
            cp_wait<0>();
        }
        __syncthreads();

        const uint32_t sb = smem + (uint32_t)(kt & 1) * 32768;
#pragma unroll
        for (int ks = 0; ks < 2; ++ks) {
            uint32_t aH[4][4], aL[4][4], bH[4][2], bL[4][2];
#pragma unroll
            for (int i = 0; i < 4; ++i)
                ldsm4(lds_addr(sb, wm * 64 + i * 16, ks, lane),
                      aH[i][0], aH[i][1], aH[i][2], aH[i][3]);
#pragma unroll
            for (int j2 = 0; j2 < 2; ++j2) {
                uint32_t r0, r1, r2, r3;
                ldsm4(lds_addr(sb + 16384, wn * 32 + j2 * 16, ks, lane), r0, r1, r2, r3);
                bH[j2 * 2 + 0][0] = r0; bH[j2 * 2 + 0][1] = r2;
                bH[j2 * 2 + 1][0] = r1; bH[j2 * 2 + 1][1] = r3;
                ldsm4(lds_addr(sb + 24576, wn * 32 + j2 * 16, ks, lane), r0, r1, r2, r3);
                bL[j2 * 2 + 0][0] = r0; bL[j2 * 2 + 0][1] = r2;
                bL[j2 * 2 + 1][0] = r1; bL[j2 * 2 + 1][1] = r3;
            }
#pragma unroll
            for (int i = 0; i < 4; ++i)
#pragma unroll
                for (int j = 0; j < 4; ++j) {
                    mma16816(acc[i][j], aH[i], bH[j][0], bH[j][1]);
                    mma16816(acc[i][j], aH[i], bL[j][0], bL[j][1]);
                }
#pragma unroll
            for (int i = 0; i < 4; ++i)
                ldsm4(lds_addr(sb + 8192, wm * 64 + i * 16, ks, lane),
                      aL[i][0], aL[i][1], aL[i][2], aL[i][3]);
#pragma unroll
            for (int i = 0; i < 4; ++i)
#pragma unroll
                for (int j = 0; j < 4; ++j)
                    mma16816(acc[i][j], aL[i], bH[j][0], bH[j][1]);
        }
        __syncthreads();
    }

    // epilogue
    const size_t growb = (size_t)bm * 128 + wm * 64;
    const int    gcolb = bn * 128 + wn * 32;
#pragma unroll
    for (int i = 0; i < 4; ++i) {
        const size_t r0 = growb + i * 16 + (lane >> 2);
#pragma unroll
        for (int j = 0; j < 4; ++j) {
            const int col = gcolb + j * 8 + (lane & 3) * 2;
            float b0 = 0.f, b1 = 0.f;
            if (bias) { b0 = bias[col]; b1 = bias[col + 1]; }
            const float v00 = acc[i][j][0] * alpha + b0;
            const float v01 = acc[i][j][1] * alpha + b1;
            const float v10 = acc[i][j][2] * alpha + b0;
            const float v11 = acc[i][j][3] * alpha + b1;
            const size_t o0 = (size_t)z * sC + r0 * N + col;
            const size_t o1 = o0 + (size_t)8 * N;
            if (SPLITOUT) {
                __nv_bfloat16 h0, l0, h1, l1;
                split2(v00, h0, l0); split2(v01, h1, l1);
                *reinterpret_cast<__nv_bfloat162*>(Ch + o0) = __nv_bfloat162(h0, h1);
                *reinterpret_cast<__nv_bfloat162*>(Cl + o0) = __nv_bfloat162(l0, l1);
                split2(v10, h0, l0); split2(v11, h1, l1);
                *reinterpret_cast<__nv_bfloat162*>(Ch + o1) = __nv_bfloat162(h0, h1);
                *reinterpret_cast<__nv_bfloat162*>(Cl + o1) = __nv_bfloat162(l0, l1);
            } else {
                *reinterpret_cast<float2*>(Cf + o0) = make_float2(v00, v01);
                *reinterpret_cast<float2*>(Cf + o1) = make_float2(v10, v11);
            }
        }
    }
}

// ---------------------------------------------------------------------------
// fp32 -> (hi, lo) bf16 split, vectorized by 4
// ---------------------------------------------------------------------------
__global__ __launch_bounds__(256) void split_f32(
    const float4* __restrict__ in, __nv_bfloat16* __restrict__ h,
    __nv_bfloat16* __restrict__ l, size_t n4)
{
    size_t i = (size_t)blockIdx.x * blockDim.x + threadIdx.x;
    if (i >= n4) return;
    float4 v = in[i];
    __align__(8) __nv_bfloat16 hb[4], lb[4];
    split2(v.x, hb[0], lb[0]);
    split2(v.y, hb[1], lb[1]);
    split2(v.z, hb[2], lb[2]);
    split2(v.w, hb[3], lb[3]);
    reinterpret_cast<uint2*>(h)[i] = *reinterpret_cast<uint2*>(hb);
    reinterpret_cast<uint2*>(l)[i] = *reinterpret_cast<uint2*>(lb);
}

// ---------------------------------------------------------------------------
// Transpose + split: in [R,C] fp32 -> out hi/lo [C,R] bf16 (batched via z)
// ---------------------------------------------------------------------------
__global__ __launch_bounds__(256) void transpose_split(
    const float* __restrict__ in, __nv_bfloat16* __restrict__ hT,
    __nv_bfloat16* __restrict__ lT, int R, int C)
{
    __shared__ float t[32][33];
    const size_t zoff = (size_t)blockIdx.z * R * C;
    const int r0 = blockIdx.y * 32, c0 = blockIdx.x * 32;
    const int tx = threadIdx.x, ty = threadIdx.y;   // (32, 8)
#pragma unroll
    for (int j = 0; j < 4; ++j)
        t[ty + 8 * j][tx] = in[zoff + (size_t)(r0 + ty + 8 * j) * C + c0 + tx];
    __syncthreads();
#pragma unroll
    for (int j = 0; j < 4; ++j) {
        float v = t[tx][ty + 8 * j];
        __nv_bfloat16 h, l;
        split2(v, h, l);
        size_t o = zoff + (size_t)(c0 + ty + 8 * j) * R + r0 + tx;
        hT[o] = h;
        lT[o] = l;
    }
}

// ---------------------------------------------------------------------------
// Row softmax over 2048 cols, fp32 in, split bf16 out.
// ---------------------------------------------------------------------------
__global__ __launch_bounds__(256) void softmax_split(
    const float* __restrict__ Sf, __nv_bfloat16* __restrict__ Sh,
    __nv_bfloat16* __restrict__ Sl)
{
    const size_t base = (size_t)blockIdx.x * SEQ;
    const int tid = threadIdx.x;

    float v[8];
    float m = -INFINITY;
#pragma unroll
    for (int i = 0; i < 8; ++i) {
        v[i] = Sf[base + tid + i * 256];
        m = fmaxf(m, v[i]);
    }

    __shared__ float red[256];
    red[tid] = m;
    __syncthreads();
#pragma unroll
    for (int s = 128; s > 0; s >>= 1) {
        if (tid < s) red[tid] = fmaxf(red[tid], red[tid + s]);
        __syncthreads();
    }
    m = red[0];
    __syncthreads();

    float sum = 0.f;
#pragma unroll
    for (int i = 0; i < 8; ++i) {
        v[i] = expf(v[i] - m);
        sum += v[i];
    }
    red[tid] = sum;
    __syncthreads();
#pragma unroll
    for (int s = 128; s > 0; s >>= 1) {
        if (tid < s) red[tid] += red[tid + s];
        __syncthreads();
    }
    const float inv = 1.0f / red[0];
#pragma unroll
    for (int i = 0; i < 8; ++i) {
        float p = v[i] * inv;
        __nv_bfloat16 h, l;
        split2(p, h, l);
        Sh[base + tid + i * 256] = h;
        Sl[base + tid + i * 256] = l;
    }
}

// ---------------------------------------------------------------------------
extern "C" void kernel_launch(void* const* d_in, const int* in_sizes, int n_in,
                              void* d_out, int out_size)
{
    (void)in_sizes; (void)n_in; (void)out_size;

    const float* X  = (const float*)d_in[0];
    const float* Wq = (const float*)d_in[1];
    const float* bq = (const float*)d_in[2];
    const float* Wk = (const float*)d_in[3];
    const float* bk = (const float*)d_in[4];
    const float* Wv = (const float*)d_in[5];
    const float* bv = (const float*)d_in[6];
    const float* Wh = (const float*)d_in[7];
    const float* bh = (const float*)d_in[8];
    float* out = (float*)d_out;

    __nv_bfloat16 *Xh, *Xl, *Wqh, *Wql, *Wkh, *Wkl, *Wvh, *Wvl, *Whh, *Whl;
    __nv_bfloat16 *Qh, *Ql, *Kh, *Kl, *Vth, *Vtl, *Sh, *Sl, *Ch, *Cl;
    float *Vf, *Sf;
    cudaGetSymbolAddress((void**)&Xh,  g_Xh);  cudaGetSymbolAddress((void**)&Xl,  g_Xl);
    cudaGetSymbolAddress((void**)&Wqh, g_Wqh); cudaGetSymbolAddress((void**)&Wql, g_Wql);
    cudaGetSymbolAddress((void**)&Wkh, g_Wkh); cudaGetSymbolAddress((void**)&Wkl, g_Wkl);
    cudaGetSymbolAddress((void**)&Wvh, g_Wvh); cudaGetSymbolAddress((void**)&Wvl, g_Wvl);
    cudaGetSymbolAddress((void**)&Whh, g_Whh); cudaGetSymbolAddress((void**)&Whl, g_Whl);
    cudaGetSymbolAddress((void**)&Qh,  g_Qh);  cudaGetSymbolAddress((void**)&Ql,  g_Ql);
    cudaGetSymbolAddress((void**)&Kh,  g_Kh);  cudaGetSymbolAddress((void**)&Kl,  g_Kl);
    cudaGetSymbolAddress((void**)&Vf,  g_Vf);
    cudaGetSymbolAddress((void**)&Vth, g_Vth); cudaGetSymbolAddress((void**)&Vtl, g_Vtl);
    cudaGetSymbolAddress((void**)&Sf,  g_Sf);
    cudaGetSymbolAddress((void**)&Sh,  g_Sh);  cudaGetSymbolAddress((void**)&Sl,  g_Sl);
    cudaGetSymbolAddress((void**)&Ch,  g_Ch);  cudaGetSymbolAddress((void**)&Cl,  g_Cl);

    cudaFuncSetAttribute(gemm_mma<true>,  cudaFuncAttributeMaxDynamicSharedMemorySize, GEMM_SMEM);
    cudaFuncSetAttribute(gemm_mma<false>, cudaFuncAttributeMaxDynamicSharedMemorySize, GEMM_SMEM);

    const dim3 blk(256);
    const float scale = 1.0f / 32.0f;   // 1/sqrt(1024)

    // 1) split X
    split_f32<<<(MTOT * HID / 4 + 255) / 256, blk>>>(
        (const float4*)X, Xh, Xl, (size_t)MTOT * HID / 4);

    // 2) transpose+split weights -> [N,K] K-major
    dim3 tgw(HID / 32, HID / 32, 1), tblk(32, 8);
    transpose_split<<<tgw, tblk>>>(Wq, Wqh, Wql, HID, HID);
    transpose_split<<<tgw, tblk>>>(Wk, Wkh, Wkl, HID, HID);
    transpose_split<<<tgw, tblk>>>(Wv, Wvh, Wvl, HID, HID);
    transpose_split<<<tgw, tblk>>>(Wh, Whh, Whl, HID, HID);

    // 3) projections (M=8192, N=1024, K=1024)
    dim3 gp(HID / 128, MTOT / 128, 1);
    gemm_mma<true ><<<gp, blk, GEMM_SMEM>>>(Xh, Xl, Wqh, Wql, bq, nullptr, Qh, Ql,
                                            HID, HID, 0, 0, 0, 1.f);
    gemm_mma<true ><<<gp, blk, GEMM_SMEM>>>(Xh, Xl, Wkh, Wkl, bk, nullptr, Kh, Kl,
                                            HID, HID, 0, 0, 0, 1.f);
    gemm_mma<false><<<gp, blk, GEMM_SMEM>>>(Xh, Xl, Wvh, Wvl, bv, Vf, nullptr, nullptr,
                                            HID, HID, 0, 0, 0, 1.f);

    // 4) V -> V^T (per batch) with split
    dim3 tgv(HID / 32, SEQ / 32, BATCH);
    transpose_split<<<tgv, tblk>>>(Vf, Vth, Vtl, SEQ, HID);

    // 5) scores = scale * Q @ K^T (batched) -> fp32
    dim3 gs(SEQ / 128, SEQ / 128, BATCH);
    gemm_mma<false><<<gs, blk, GEMM_SMEM>>>(Qh, Ql, Kh, Kl, nullptr, Sf, nullptr, nullptr,
                                            SEQ, HID,
                                            (size_t)SEQ * HID, (size_t)SEQ * HID,
                                            (size_t)SEQ * SEQ, scale);

    // 6) softmax + split
    softmax_split<<<BATCH * SEQ, blk>>>(Sf, Sh, Sl);

    // 7) context = attn @ V (batched, K=2048) -> split
    dim3 gc(HID / 128, SEQ / 128, BATCH);
    gemm_mma<true ><<<gc, blk, GEMM_SMEM>>>(Sh, Sl, Vth, Vtl, nullptr, nullptr, Ch, Cl,
                                            HID, SEQ,
                                            (size_t)SEQ * SEQ, (size_t)HID * SEQ,
                                            (size_t)SEQ * HID, 1.f);

    // 8) y = context @ Wh + bh -> d_out fp32
    dim3 go(HID / 128, MTOT / 128, 1);
    gemm_mma<false><<<go, blk, GEMM_SMEM>>>(Ch, Cl, Whh, Whl, bh, out, nullptr, nullptr,
                                            HID, HID, 0, 0, 0, 1.f);
}